// round 2
// baseline (speedup 1.0000x reference)
#include <cuda_runtime.h>
#include <cuda_bf16.h>
#include <math.h>

#define EMBED 1024
#define NHEAD 16
#define DK    64
#define BATCH 4
#define SEQ   2048
#define MTOK  (BATCH*SEQ)   // 8192

// -------- scratch (device globals; no allocation allowed) --------
__device__ float g_q[(size_t)BATCH*NHEAD*SEQ*DK];   // [b,h,s,d], pre-scaled by 1/sqrt(DK)
__device__ float g_k[(size_t)BATCH*NHEAD*SEQ*DK];
__device__ float g_v[(size_t)BATCH*NHEAD*SEQ*DK];
__device__ float g_attn[(size_t)MTOK*EMBED];        // [b,s,e] attention output

// -------- helpers --------
__device__ __forceinline__ unsigned f2tf(float f) {
    unsigned u; asm("cvt.rna.tf32.f32 %0, %1;" : "=r"(u) : "f"(f)); return u;
}

__device__ __forceinline__ void mma8(float* c, const unsigned* a, const unsigned* b) {
    asm volatile("mma.sync.aligned.m16n8k8.row.col.f32.tf32.tf32.f32 "
        "{%0,%1,%2,%3},{%4,%5,%6,%7},{%8,%9},{%0,%1,%2,%3};"
        : "+f"(c[0]), "+f"(c[1]), "+f"(c[2]), "+f"(c[3])
        : "r"(a[0]), "r"(a[1]), "r"(a[2]), "r"(a[3]), "r"(b[0]), "r"(b[1]));
}

// swizzles (4-float granularity) to limit LDS bank conflicts
__device__ __forceinline__ int sw16(int m, int k) {
    return m*16 + (((((k) >> 2) ^ (m & 3)) << 2) | (k & 3));
}
__device__ __forceinline__ int sw64(int r, int c) {
    return r*64 + (((((c) >> 2) ^ (r & 7)) << 2) | (c & 3));
}

// ============ 128x128 NT GEMM core (C = A[M,K] * W[N,K]^T), K=1024 ============
// 256 threads = 8 warps in 4(m) x 2(n); warp tile 32x64 = 2 mtiles x 8 ntiles.
__device__ __forceinline__ void gemm_core(
    const float* __restrict__ A, const float* __restrict__ W,
    int row0, int col0, unsigned* As, unsigned* Bs, float acc[2][8][4])
{
    const int K = EMBED;
    int tid  = threadIdx.x;
    int lane = tid & 31, wid = tid >> 5;
    int g = lane >> 2, tg = lane & 3;
    int wm = wid >> 1, wn = wid & 1;

    #pragma unroll
    for (int mt = 0; mt < 2; mt++)
        #pragma unroll
        for (int nt = 0; nt < 8; nt++)
            #pragma unroll
            for (int i = 0; i < 4; i++) acc[mt][nt][i] = 0.f;

    int fr[2], fc[2];
    #pragma unroll
    for (int i = 0; i < 2; i++) { int f = tid + 256*i; fr[i] = f >> 2; fc[i] = (f & 3) * 4; }

    float4 pa[2], pb[2];
    auto LDG = [&](int kb) {
        #pragma unroll
        for (int i = 0; i < 2; i++) {
            pa[i] = *(const float4*)(A + (size_t)(row0 + fr[i]) * K + kb + fc[i]);
            pb[i] = *(const float4*)(W + (size_t)(col0 + fr[i]) * K + kb + fc[i]);
        }
    };
    auto STS = [&]() {
        #pragma unroll
        for (int i = 0; i < 2; i++) {
            int ad = sw16(fr[i], fc[i]);
            *(uint4*)(As + ad) = make_uint4(f2tf(pa[i].x), f2tf(pa[i].y), f2tf(pa[i].z), f2tf(pa[i].w));
            *(uint4*)(Bs + ad) = make_uint4(f2tf(pb[i].x), f2tf(pb[i].y), f2tf(pb[i].z), f2tf(pb[i].w));
        }
    };

    LDG(0); STS(); __syncthreads();
    const int NK = K / 16;
    for (int kt = 0; kt < NK; kt++) {
        if (kt + 1 < NK) LDG((kt + 1) * 16);
        #pragma unroll
        for (int kk = 0; kk < 16; kk += 8) {
            unsigned a[2][4], b[8][2];
            #pragma unroll
            for (int mt = 0; mt < 2; mt++) {
                int r = wm*32 + mt*16 + g;
                a[mt][0] = As[sw16(r,     kk + tg)];
                a[mt][1] = As[sw16(r + 8, kk + tg)];
                a[mt][2] = As[sw16(r,     kk + tg + 4)];
                a[mt][3] = As[sw16(r + 8, kk + tg + 4)];
            }
            #pragma unroll
            for (int nt = 0; nt < 8; nt++) {
                int n = wn*64 + nt*8 + g;
                b[nt][0] = Bs[sw16(n, kk + tg)];
                b[nt][1] = Bs[sw16(n, kk + tg + 4)];
            }
            #pragma unroll
            for (int mt = 0; mt < 2; mt++)
                #pragma unroll
                for (int nt = 0; nt < 8; nt++)
                    mma8(acc[mt][nt], a[mt], b[nt]);
        }
        __syncthreads();
        if (kt + 1 < NK) { STS(); __syncthreads(); }
    }
}

// ============ Kernel 1: fused QKV projections (grid.z picks Q/K/V) ============
__global__ __launch_bounds__(256) void qkv_kernel(
    const float* __restrict__ x,
    const float* __restrict__ Wq, const float* __restrict__ Wk, const float* __restrict__ Wv)
{
    __shared__ unsigned As[128*16], Bs[128*16];
    int row0 = blockIdx.y * 128, col0 = blockIdx.x * 128;
    const float* W = (blockIdx.z == 0) ? Wq : (blockIdx.z == 1 ? Wk : Wv);
    float* dst     = (blockIdx.z == 0) ? g_q : (blockIdx.z == 1 ? g_k : g_v);
    float scale    = (blockIdx.z == 0) ? 0.125f : 1.0f;   // 1/sqrt(64) folded into Q

    float acc[2][8][4];
    gemm_core(x, W, row0, col0, As, Bs, acc);

    int lane = threadIdx.x & 31, wid = threadIdx.x >> 5;
    int g = lane >> 2, tg = lane & 3, wm = wid >> 1, wn = wid & 1;
    #pragma unroll
    for (int mt = 0; mt < 2; mt++) {
        int r = row0 + wm*32 + mt*16 + g;      // token index
        int bb = r >> 11, ss = r & 2047;
        #pragma unroll
        for (int nt = 0; nt < 8; nt++) {
            int c = col0 + wn*64 + nt*8 + 2*tg;  // feature index
            int h = c >> 6, d = c & 63;
            float* p0 = dst + (((size_t)(bb*NHEAD + h) * SEQ + ss) * DK + d);
            float* p1 = dst + (((size_t)(bb*NHEAD + h) * SEQ + ss + 8) * DK + d);
            p0[0] = acc[mt][nt][0] * scale; p0[1] = acc[mt][nt][1] * scale;
            p1[0] = acc[mt][nt][2] * scale; p1[1] = acc[mt][nt][3] * scale;
        }
    }
}

// ============ Kernel 2: flash attention (64q x 64k tiles, online softmax) ============
// grid (SEQ/64, BATCH*NHEAD), 128 threads = 4 warps, each warp owns 16 q-rows.
__global__ __launch_bounds__(128) void attn_kernel()
{
    __shared__ unsigned Qs[64*64];
    __shared__ unsigned KPs[64*64];   // K tile, later reused for P tile
    __shared__ unsigned Vs[64*64];

    int qt = blockIdx.x, bh = blockIdx.y;
    const float* Qp = g_q + (size_t)bh * SEQ * DK + (size_t)qt * 64 * DK;
    const float* Kp = g_k + (size_t)bh * SEQ * DK;
    const float* Vp = g_v + (size_t)bh * SEQ * DK;

    int tid = threadIdx.x, lane = tid & 31, wid = tid >> 5;
    int g = lane >> 2, tg = lane & 3;
    int r0 = wid*16 + g;     // this thread's first q-row within tile (second is r0+8)

    // load Q tile (convert to tf32, swizzled)
    #pragma unroll
    for (int i = 0; i < 8; i++) {
        int f = tid + 128*i;           // float4 index 0..1023
        int r = f >> 4, c4 = f & 15;
        float4 v = *(const float4*)(Qp + r*64 + c4*4);
        int ad = r*64 + ((c4 ^ (r & 7)) << 2);
        *(uint4*)(Qs + ad) = make_uint4(f2tf(v.x), f2tf(v.y), f2tf(v.z), f2tf(v.w));
    }

    float o[8][4];
    #pragma unroll
    for (int nt = 0; nt < 8; nt++)
        #pragma unroll
        for (int i = 0; i < 4; i++) o[nt][i] = 0.f;
    float m0 = -1e30f, m1 = -1e30f, l0 = 0.f, l1 = 0.f;

    for (int kt = 0; kt < SEQ/64; kt++) {
        // fill K -> KPs, V -> Vs
        #pragma unroll
        for (int i = 0; i < 8; i++) {
            int f = tid + 128*i;
            int r = f >> 4, c4 = f & 15;
            int ad = r*64 + ((c4 ^ (r & 7)) << 2);
            float4 kv = *(const float4*)(Kp + (size_t)(kt*64 + r)*64 + c4*4);
            *(uint4*)(KPs + ad) = make_uint4(f2tf(kv.x), f2tf(kv.y), f2tf(kv.z), f2tf(kv.w));
            float4 vv = *(const float4*)(Vp + (size_t)(kt*64 + r)*64 + c4*4);
            *(uint4*)(Vs + ad) = make_uint4(f2tf(vv.x), f2tf(vv.y), f2tf(vv.z), f2tf(vv.w));
        }
        __syncthreads();

        // S = Q * K^T  (warp computes 16x64 stripe)
        float s[8][4];
        #pragma unroll
        for (int nt = 0; nt < 8; nt++)
            #pragma unroll
            for (int i = 0; i < 4; i++) s[nt][i] = 0.f;
        #pragma unroll
        for (int kk = 0; kk < 64; kk += 8) {
            unsigned a[4], b[8][2];
            a[0] = Qs[sw64(r0,     kk + tg)];
            a[1] = Qs[sw64(r0 + 8, kk + tg)];
            a[2] = Qs[sw64(r0,     kk + tg + 4)];
            a[3] = Qs[sw64(r0 + 8, kk + tg + 4)];
            #pragma unroll
            for (int nt = 0; nt < 8; nt++) {
                b[nt][0] = KPs[sw64(nt*8 + g, kk + tg)];
                b[nt][1] = KPs[sw64(nt*8 + g, kk + tg + 4)];
            }
            #pragma unroll
            for (int nt = 0; nt < 8; nt++) mma8(s[nt], a, b[nt]);
        }

        // online softmax (rows r0, r0+8); quad (tg) shuffle reductions
        float ml0 = -1e30f, ml1 = -1e30f;
        #pragma unroll
        for (int nt = 0; nt < 8; nt++) {
            ml0 = fmaxf(ml0, fmaxf(s[nt][0], s[nt][1]));
            ml1 = fmaxf(ml1, fmaxf(s[nt][2], s[nt][3]));
        }
        ml0 = fmaxf(ml0, __shfl_xor_sync(0xffffffffu, ml0, 1));
        ml0 = fmaxf(ml0, __shfl_xor_sync(0xffffffffu, ml0, 2));
        ml1 = fmaxf(ml1, __shfl_xor_sync(0xffffffffu, ml1, 1));
        ml1 = fmaxf(ml1, __shfl_xor_sync(0xffffffffu, ml1, 2));
        float mn0 = fmaxf(m0, ml0), mn1 = fmaxf(m1, ml1);
        float al0 = __expf(m0 - mn0), al1 = __expf(m1 - mn1);
        m0 = mn0; m1 = mn1;
        float sum0 = 0.f, sum1 = 0.f;
        #pragma unroll
        for (int nt = 0; nt < 8; nt++) {
            s[nt][0] = __expf(s[nt][0] - mn0); sum0 += s[nt][0];
            s[nt][1] = __expf(s[nt][1] - mn0); sum0 += s[nt][1];
            s[nt][2] = __expf(s[nt][2] - mn1); sum1 += s[nt][2];
            s[nt][3] = __expf(s[nt][3] - mn1); sum1 += s[nt][3];
        }
        sum0 += __shfl_xor_sync(0xffffffffu, sum0, 1);
        sum0 += __shfl_xor_sync(0xffffffffu, sum0, 2);
        sum1 += __shfl_xor_sync(0xffffffffu, sum1, 1);
        sum1 += __shfl_xor_sync(0xffffffffu, sum1, 2);
        l0 = l0 * al0 + sum0;
        l1 = l1 * al1 + sum1;
        #pragma unroll
        for (int nt = 0; nt < 8; nt++) {
            o[nt][0] *= al0; o[nt][1] *= al0;
            o[nt][2] *= al1; o[nt][3] *= al1;
        }

        __syncthreads();   // all warps done reading K tile
        // store P into KPs (tf32)
        #pragma unroll
        for (int nt = 0; nt < 8; nt++) {
            int c = nt*8 + 2*tg;
            KPs[sw64(r0,     c)]     = f2tf(s[nt][0]);
            KPs[sw64(r0,     c + 1)] = f2tf(s[nt][1]);
            KPs[sw64(r0 + 8, c)]     = f2tf(s[nt][2]);
            KPs[sw64(r0 + 8, c + 1)] = f2tf(s[nt][3]);
        }
        __syncthreads();

        // O += P * V  (A = P [64q x 64k], B = V [64k x 64d])
        #pragma unroll
        for (int kk = 0; kk < 64; kk += 8) {
            unsigned a[4], b[8][2];
            a[0] = KPs[sw64(r0,     kk + tg)];
            a[1] = KPs[sw64(r0 + 8, kk + tg)];
            a[2] = KPs[sw64(r0,     kk + tg + 4)];
            a[3] = KPs[sw64(r0 + 8, kk + tg + 4)];
            #pragma unroll
            for (int nt = 0; nt < 8; nt++) {
                b[nt][0] = Vs[sw64(kk + tg,     nt*8 + g)];
                b[nt][1] = Vs[sw64(kk + tg + 4, nt*8 + g)];
            }
            #pragma unroll
            for (int nt = 0; nt < 8; nt++) mma8(o[nt], a, b[nt]);
        }
        __syncthreads();   // protect KPs/Vs before next tile's fill
    }

    // epilogue: normalize and write to g_attn[b, s, h*64+d]
    float inv0 = 1.f / l0, inv1 = 1.f / l1;
    int bb = bh >> 4, h = bh & 15;
    int q0 = qt*64 + r0;
    float* base0 = g_attn + ((size_t)(bb*SEQ + q0) * EMBED) + h*64;
    float* base1 = base0 + (size_t)8 * EMBED;
    #pragma unroll
    for (int nt = 0; nt < 8; nt++) {
        int d = nt*8 + 2*tg;
        base0[d]     = o[nt][0] * inv0;
        base0[d + 1] = o[nt][1] * inv0;
        base1[d]     = o[nt][2] * inv1;
        base1[d + 1] = o[nt][3] * inv1;
    }
}

// ============ Kernel 3: output projection ============
__global__ __launch_bounds__(256) void oproj_kernel(const float* __restrict__ Wo, float* __restrict__ out)
{
    __shared__ unsigned As[128*16], Bs[128*16];
    int row0 = blockIdx.y * 128, col0 = blockIdx.x * 128;
    float acc[2][8][4];
    gemm_core(g_attn, Wo, row0, col0, As, Bs, acc);

    int lane = threadIdx.x & 31, wid = threadIdx.x >> 5;
    int g = lane >> 2, tg = lane & 3, wm = wid >> 1, wn = wid & 1;
    #pragma unroll
    for (int mt = 0; mt < 2; mt++) {
        int r = row0 + wm*32 + mt*16 + g;
        #pragma unroll
        for (int nt = 0; nt < 8; nt++) {
            int c = col0 + wn*64 + nt*8 + 2*tg;
            float* p0 = out + (size_t)r * EMBED + c;
            float* p1 = out + (size_t)(r + 8) * EMBED + c;
            p0[0] = acc[mt][nt][0]; p0[1] = acc[mt][nt][1];
            p1[0] = acc[mt][nt][2]; p1[1] = acc[mt][nt][3];
        }
    }
}

// ============ launch ============
extern "C" void kernel_launch(void* const* d_in, const int* in_sizes, int n_in,
                              void* d_out, int out_size)
{
    const float* x  = (const float*)d_in[0];
    const float* Wq = (const float*)d_in[1];
    const float* Wk = (const float*)d_in[2];
    const float* Wv = (const float*)d_in[3];
    const float* Wo = (const float*)d_in[4];
    float* out = (float*)d_out;

    qkv_kernel<<<dim3(EMBED/128, MTOK/128, 3), 256>>>(x, Wq, Wk, Wv);
    attn_kernel<<<dim3(SEQ/64, BATCH*NHEAD), 128>>>();
    oproj_kernel<<<dim3(EMBED/128, MTOK/128), 256>>>(Wo, out);
}